// round 11
// baseline (speedup 1.0000x reference)
#include <cuda_runtime.h>

// ---------------- problem constants ----------------
#define N_EMB   50000
#define B_Q     512
#define E_DIM   16
#define K_NN    20
#define NCHUNK  96
#define CHUNK   521           // 96*521 = 50016 >= 50000; tiles 256+256+9 (pad->12)
#define TILE    256
#define QPB     128
#define CAP     2048
#define BUFD    16            // per-thread smem survivor slots per tile
#define WIN     1024          // prep sample window
#define FLT_BIG 3.402823466e+38f
#define FULLMASK 0xffffffffu

typedef unsigned long long u64;

// packed f32x2 helpers
#define FMA2(d, a, b, c) asm("fma.rn.f32x2 %0, %1, %2, %3;" : "=l"(d) : "l"(a), "l"(b), "l"(c))
#define PACK2(d, lo, hi) asm("mov.b64 %0, {%1, %2};" : "=l"(d) : "f"(lo), "f"(hi))
#define UNPACK2(lo, hi, v) asm("mov.b64 {%0, %1}, %2;" : "=f"(lo), "=f"(hi) : "l"(v))
#define PACKFI(d, f, i) asm("mov.b64 %0, {%1, %2};" : "=l"(d) : "f"(f), "r"(i))
#define UNPACKFI(f, i, v) asm("mov.b64 {%0, %1}, %2;" : "=f"(f), "=r"(i) : "l"(v))

// ---------------- scratch ----------------
__device__ float g_tau [2 * B_Q];
__device__ int   g_cnt [2 * B_Q];
__device__ u64   g_f   [(size_t)2 * B_Q * CAP];   // packed (float score, int idx)

// ---------------- helpers ----------------
template <int S>
__device__ __forceinline__ void sinsN(float (&rv)[S], int (&ri)[S], float s, int j) {
    float cv = s; int ci = j;
    #pragma unroll
    for (int k = 0; k < S; k++) {
        bool sm = cv < rv[k];
        float tv = rv[k]; int ti = ri[k];
        rv[k] = sm ? cv : rv[k];
        ri[k] = sm ? ci : ri[k];
        cv = sm ? tv : cv;
        ci = sm ? ti : ci;
    }
}

template <int S>
__device__ __forceinline__ void popN(float (&rv)[S], int (&ri)[S]) {
    #pragma unroll
    for (int k = 0; k < S - 1; k++) { rv[k] = rv[k + 1]; ri[k] = ri[k + 1]; }
    rv[S - 1] = FLT_BIG; ri[S - 1] = 0;
}

__device__ __forceinline__ void wmin(float& v, int& id, int& ln) {
    #pragma unroll
    for (int off = 16; off; off >>= 1) {
        float ov = __shfl_xor_sync(FULLMASK, v,  off);
        int  oid = __shfl_xor_sync(FULLMASK, id, off);
        int  oln = __shfl_xor_sync(FULLMASK, ln, off);
        if (ov < v) { v = ov; id = oid; ln = oln; }
    }
}

__device__ __forceinline__ void wminv(float& v) {
    #pragma unroll
    for (int off = 16; off; off >>= 1) {
        float ov = __shfl_xor_sync(FULLMASK, v, off);
        v = (ov < v) ? ov : v;
    }
}

__device__ __forceinline__ void load_q_neg2(const float* emb, int self, u64 (&an)[8]) {
    const float4* av = reinterpret_cast<const float4*>(emb) + (size_t)self * 4;
    float4 a0 = av[0], a1 = av[1], a2 = av[2], a3 = av[3];
    PACK2(an[0], -a0.x, -a0.y); PACK2(an[1], -a0.z, -a0.w);
    PACK2(an[2], -a1.x, -a1.y); PACK2(an[3], -a1.z, -a1.w);
    PACK2(an[4], -a2.x, -a2.y); PACK2(an[5], -a2.z, -a2.w);
    PACK2(an[6], -a3.x, -a3.y); PACK2(an[7], -a3.z, -a3.w);
}

// score = 0.5|e|^2 - a.e with acc pre-init (0.5n, 0); two accumulator chains
__device__ __forceinline__ float score8(const ulonglong2* __restrict__ e2, const u64 an[8], u64 acc0) {
    ulonglong2 u0 = e2[0], u1 = e2[1], u2 = e2[2], u3 = e2[3];
    u64 acc1 = 0ull;
    FMA2(acc0, u0.x, an[0], acc0); FMA2(acc1, u0.y, an[1], acc1);
    FMA2(acc0, u1.x, an[2], acc0); FMA2(acc1, u1.y, an[3], acc1);
    FMA2(acc0, u2.x, an[4], acc0); FMA2(acc1, u2.y, an[5], acc1);
    FMA2(acc0, u3.x, an[6], acc0); FMA2(acc1, u3.y, an[7], acc1);
    float l0, h0, l1, h1;
    UNPACK2(l0, h0, acc0);
    UNPACK2(l1, h1, acc1);
    return (l0 + h0) + (l1 + h1);
}

// ============ kernel A: per-(pass,query) tau — block per query, 4 warps split window ============
__global__ __launch_bounds__(128) void prep_kernel(
    const float* __restrict__ emb0, const float* __restrict__ emb1,
    const int* __restrict__ idx0, const int* __restrict__ idx1)
{
    __shared__ float sv[32];

    const int tid  = threadIdx.x;
    const int wid  = tid >> 5;
    const int lane = tid & 31;
    const int w    = blockIdx.x;            // [0,1024)
    const int pass = w >> 9;
    const int q    = w & (B_Q - 1);

    const float* emb  = pass ? emb1 : emb0;
    const int    self = (pass ? idx1 : idx0)[q];

    u64 an[8];
    load_q_neg2(emb, self, an);
    u64 halfp;
    PACK2(halfp, 0.5f, 0.5f);

    float rv[8]; int ri[8];
    #pragma unroll
    for (int k = 0; k < 8; k++) { rv[k] = FLT_BIG; ri[k] = 0; }

    const ulonglong2* emb2 = reinterpret_cast<const ulonglong2*>(emb);

    #pragma unroll 2
    for (int i = 0; i < 8; i++) {
        int j = wid * 256 + i * 32 + lane;
        const ulonglong2* p = emb2 + (size_t)j * 4;
        ulonglong2 u0 = p[0], u1 = p[1], u2 = p[2], u3 = p[3];
        u64 h0, h1, h2, h3, h4, h5, h6, h7;
        FMA2(h0, u0.x, halfp, an[0]); FMA2(h1, u0.y, halfp, an[1]);
        FMA2(h2, u1.x, halfp, an[2]); FMA2(h3, u1.y, halfp, an[3]);
        FMA2(h4, u2.x, halfp, an[4]); FMA2(h5, u2.y, halfp, an[5]);
        FMA2(h6, u3.x, halfp, an[6]); FMA2(h7, u3.y, halfp, an[7]);
        u64 acc0 = 0ull, acc1 = 0ull;
        FMA2(acc0, u0.x, h0, acc0); FMA2(acc1, u0.y, h1, acc1);
        FMA2(acc0, u1.x, h2, acc0); FMA2(acc1, u1.y, h3, acc1);
        FMA2(acc0, u2.x, h4, acc0); FMA2(acc1, u2.y, h5, acc1);
        FMA2(acc0, u3.x, h6, acc0); FMA2(acc1, u3.y, h7, acc1);
        float l0, hh0, l1, hh1;
        UNPACK2(l0, hh0, acc0);
        UNPACK2(l1, hh1, acc1);
        float s = (l0 + hh0) + (l1 + hh1);
        if (s < rv[7] && j != self) sinsN<8>(rv, ri, s, j);
    }

    #pragma unroll
    for (int r = 0; r < 8; r++) {
        float v = rv[0]; int id = ri[0]; int ln = lane;
        wmin(v, id, ln);
        if (lane == ln) popN<8>(rv, ri);
        if (lane == 0) sv[wid * 8 + r] = v;
    }
    __syncthreads();

    if (wid == 0) {
        float v = sv[lane];
        float tau = 0.f;
        #pragma unroll
        for (int r = 0; r < 8; r++) {
            float mv = v;
            wminv(mv);
            tau = mv;
            if (v == mv) v = FLT_BIG;
        }
        if (lane == 0) { g_tau[w] = tau; g_cnt[w] = 0; }
    }
}

// ============ kernel B: filter — branch-free survivor push, exact tile bounds ============
__global__ __launch_bounds__(QPB) void filter_kernel(
    const float* __restrict__ emb0, const float* __restrict__ emb1,
    const int* __restrict__ idx0, const int* __restrict__ idx1)
{
    __shared__ float4 smE[TILE * 4];        // 16KB
    __shared__ u64    smN[TILE];            // 2KB packed (0.5n, 0)
    __shared__ u64    sbuf[BUFD * QPB];     // 16KB, layout [slot][tid]

    const int chunk = blockIdx.x;
    const int qg    = blockIdx.y;
    const int pass  = blockIdx.z;
    const int tid   = threadIdx.x;

    const float* emb = pass ? emb1 : emb0;
    const float4* emb4 = reinterpret_cast<const float4*>(emb);

    const int q    = qg * QPB + tid;
    const int t2   = pass * B_Q + q;
    const int self = (pass ? idx1 : idx0)[q];
    const float tau = g_tau[t2];

    u64 an[8];
    load_q_neg2(emb, self, an);

    const int c0 = chunk * CHUNK;
    const int c1 = min(c0 + CHUNK, N_EMB);

    for (int base = c0; base < c1; base += TILE) {
        const int nvalid = c1 - base;
        const int ncp = (min(TILE, nvalid) + 3) & ~3;   // exact padded bound
        __syncthreads();
        for (int c = tid; c < ncp; c += QPB) {
            int gj = base + c;
            if (c < nvalid) {
                const float4* gE = emb4 + (size_t)gj * 4;
                float4 v0 = gE[0], v1 = gE[1], v2 = gE[2], v3 = gE[3];
                smE[4*c] = v0; smE[4*c+1] = v1; smE[4*c+2] = v2; smE[4*c+3] = v3;
                float s = v0.x*v0.x + v0.y*v0.y + v0.z*v0.z + v0.w*v0.w
                        + v1.x*v1.x + v1.y*v1.y + v1.z*v1.z + v1.w*v1.w
                        + v2.x*v2.x + v2.y*v2.y + v2.z*v2.z + v2.w*v2.w
                        + v3.x*v3.x + v3.y*v3.y + v3.z*v3.z + v3.w*v3.w;
                u64 pn; PACK2(pn, 0.5f * s, 0.f);
                smN[c] = pn;
            } else {
                float4 z = make_float4(0.f, 0.f, 0.f, 0.f);
                smE[4*c] = z; smE[4*c+1] = z; smE[4*c+2] = z; smE[4*c+3] = z;
                u64 pn; PACK2(pn, FLT_BIG, 0.f);
                smN[c] = pn;
            }
        }
        __syncthreads();

        const ulonglong2* smE2 = reinterpret_cast<const ulonglong2*>(smE);
        int cnt = 0;

        #pragma unroll 1
        for (int cc = 0; cc < ncp; cc += 4) {
            float s0 = score8(&smE2[4*cc],      an, smN[cc]);
            float s1 = score8(&smE2[4*cc + 4],  an, smN[cc + 1]);
            float s2 = score8(&smE2[4*cc + 8],  an, smN[cc + 2]);
            float s3 = score8(&smE2[4*cc + 12], an, smN[cc + 3]);

            u64 v;
            PACKFI(v, s0, base + cc);
            sbuf[min(cnt, BUFD - 1) * QPB + tid] = v;  cnt += (s0 <= tau);
            PACKFI(v, s1, base + cc + 1);
            sbuf[min(cnt, BUFD - 1) * QPB + tid] = v;  cnt += (s1 <= tau);
            PACKFI(v, s2, base + cc + 2);
            sbuf[min(cnt, BUFD - 1) * QPB + tid] = v;  cnt += (s2 <= tau);
            PACKFI(v, s3, base + cc + 3);
            sbuf[min(cnt, BUFD - 1) * QPB + tid] = v;  cnt += (s3 <= tau);
        }

        if (cnt > 0) {
            if (cnt > BUFD) cnt = BUFD;
            int slot = atomicAdd(&g_cnt[t2], cnt);
            for (int k = 0; k < cnt; k++) {
                int o = slot + k;
                if (o < CAP) g_f[(size_t)t2 * CAP + o] = sbuf[k * QPB + tid];
            }
        }
    }
}

// ============ kernel C: exact top-20 of survivors + features + fused MLP ============
__global__ __launch_bounds__(128) void select_kernel(
    const float* __restrict__ emb0, const float* __restrict__ emb1,
    const float* __restrict__ rctx0, const float* __restrict__ rctx1,
    const int* __restrict__ idx0, const int* __restrict__ idx1,
    const float* __restrict__ mean_in, const float* __restrict__ std_in,
    const float* __restrict__ W1, const float* __restrict__ b1,
    const float* __restrict__ Wm, const float* __restrict__ bm,
    const float* __restrict__ Ws, const float* __restrict__ bs,
    float* __restrict__ out)
{
    __shared__ float sfe[2][8];

    const int wid  = threadIdx.x >> 5;
    const int lane = threadIdx.x & 31;
    const int ql   = wid >> 1;
    const int pass = wid & 1;
    const int q    = blockIdx.x * 2 + ql;
    const int t2   = pass * B_Q + q;

    const float* rctx = pass ? rctx1 : rctx0;
    const float* emb  = pass ? emb1 : emb0;
    const int    self = (pass ? idx1 : idx0)[q];

    float na;
    {
        const float4* av = reinterpret_cast<const float4*>(emb) + (size_t)self * 4;
        float4 a0 = av[0], a1 = av[1], a2 = av[2], a3 = av[3];
        na = a0.x*a0.x + a0.y*a0.y + a0.z*a0.z + a0.w*a0.w
           + a1.x*a1.x + a1.y*a1.y + a1.z*a1.z + a1.w*a1.w
           + a2.x*a2.x + a2.y*a2.y + a2.z*a2.z + a2.w*a2.w
           + a3.x*a3.x + a3.y*a3.y + a3.z*a3.z + a3.w*a3.w;
    }

    int cnt = g_cnt[t2];
    if (cnt > CAP) cnt = CAP;

    float rv[10]; int ri[10];
    #pragma unroll
    for (int k = 0; k < 10; k++) { rv[k] = FLT_BIG; ri[k] = 0; }
    const u64* GF = g_f + (size_t)t2 * CAP;
    for (int i = lane; i < cnt; i += 32) {
        u64 v = GF[i];
        float s; int j;
        UNPACKFI(s, j, v);
        if (s < rv[9] && j != self) sinsN<10>(rv, ri, s, j);
    }

    float ms = 0.f; int mj = 0;
    #pragma unroll
    for (int r = 0; r < K_NN; r++) {
        float v = rv[0]; int id = ri[0]; int ln = lane;
        wmin(v, id, ln);
        if (lane == ln) popN<10>(rv, ri);
        if (lane == r) { ms = v; mj = id; }
    }

    const bool act = lane < K_NN;
    float w = 0.f, y = 0.f;
    if (act) {
        float d2 = fmaxf(fmaf(2.f, ms, na), 0.f);
        w = expf(-(sqrtf(d2) + 0.001f));
        y = rctx[(size_t)q * N_EMB + mj];
    }
    float f1 = w, f2n = w * y, ysum = y;
    #pragma unroll
    for (int off = 16; off; off >>= 1) {
        f1   += __shfl_xor_sync(FULLMASK, f1,   off);
        f2n  += __shfl_xor_sync(FULLMASK, f2n,  off);
        ysum += __shfl_xor_sync(FULLMASK, ysum, off);
    }
    float mean = ysum * (1.0f / K_NN);
    float d = act ? (y - mean) : 0.f;
    float var = d * d;
    #pragma unroll
    for (int off = 16; off; off >>= 1) var += __shfl_xor_sync(FULLMASK, var, off);
    float f3 = sqrtf(var * (1.0f / (K_NN - 1)));

    if (lane == 0) {
        sfe[ql][pass]     = f1;
        sfe[ql][2 + pass] = f2n / f1;
        sfe[ql][4 + pass] = f3;
        if (pass == 0) {
            sfe[ql][6] = mean_in[q];
            sfe[ql][7] = std_in[q];
        }
    }
    __syncthreads();

    if (wid < 2) {
        const int mq = blockIdx.x * 2 + wid;
        float f[8];
        #pragma unroll
        for (int i = 0; i < 8; i++) f[i] = sfe[wid][i];

        float m = 0.f, sd = 0.f;
        #pragma unroll
        for (int half = 0; half < 2; half++) {
            int j = lane + half * 32;
            float acc = b1[j];
            #pragma unroll
            for (int i = 0; i < 8; i++) acc = fmaf(f[i], W1[i * 64 + j], acc);
            float h = fmaxf(acc, 0.f);
            m  = fmaf(h, Wm[j], m);
            sd = fmaf(h, Ws[j], sd);
        }
        #pragma unroll
        for (int off = 16; off; off >>= 1) {
            m  += __shfl_xor_sync(FULLMASK, m,  off);
            sd += __shfl_xor_sync(FULLMASK, sd, off);
        }
        if (lane == 0) {
            out[mq]       = m  + bm[0];
            out[B_Q + mq] = sd + bs[0];
        }
    }
}

// ---------------- launcher ----------------
extern "C" void kernel_launch(void* const* d_in, const int* in_sizes, int n_in,
                              void* d_out, int out_size)
{
    const float* emb0    = (const float*)d_in[0];
    const float* emb1    = (const float*)d_in[1];
    const float* rctx0   = (const float*)d_in[2];
    const float* rctx1   = (const float*)d_in[3];
    const int*   idx0    = (const int*)d_in[4];
    const int*   idx1    = (const int*)d_in[5];
    const float* mean_in = (const float*)d_in[6];
    const float* std_in  = (const float*)d_in[7];
    const float* W1      = (const float*)d_in[8];
    const float* b1      = (const float*)d_in[9];
    const float* Wm      = (const float*)d_in[10];
    const float* bm      = (const float*)d_in[11];
    const float* Ws      = (const float*)d_in[12];
    const float* bs      = (const float*)d_in[13];
    float* out = (float*)d_out;

    prep_kernel<<<2 * B_Q, 128>>>(emb0, emb1, idx0, idx1);

    dim3 g1(NCHUNK, B_Q / QPB, 2);
    filter_kernel<<<g1, QPB>>>(emb0, emb1, idx0, idx1);

    select_kernel<<<B_Q / 2, 128>>>(emb0, emb1, rctx0, rctx1, idx0, idx1,
                                    mean_in, std_in,
                                    W1, b1, Wm, bm, Ws, bs, out);
}

// round 12
// speedup vs baseline: 1.5855x; 1.5855x over previous
#include <cuda_runtime.h>

// ---------------- problem constants ----------------
#define N_EMB   50000
#define B_Q     512
#define E_DIM   16
#define K_NN    20
#define NCHUNK  64
#define CHUNK   782           // 64*782 = 50048 >= 50000; tiles 256*3 + 14 (pad->16)
#define TILE    256
#define QPB     128
#define CAP     2048
#define BUFD    16            // per-thread smem survivor slots per tile
#define WIN     1024          // prep sample window
#define FLT_BIG 3.402823466e+38f
#define FULLMASK 0xffffffffu

typedef unsigned long long u64;

// packed f32x2 helpers
#define FMA2(d, a, b, c) asm("fma.rn.f32x2 %0, %1, %2, %3;" : "=l"(d) : "l"(a), "l"(b), "l"(c))
#define PACK2(d, lo, hi) asm("mov.b64 %0, {%1, %2};" : "=l"(d) : "f"(lo), "f"(hi))
#define UNPACK2(lo, hi, v) asm("mov.b64 {%0, %1}, %2;" : "=f"(lo), "=f"(hi) : "l"(v))
#define PACKFI(d, f, i) asm("mov.b64 %0, {%1, %2};" : "=l"(d) : "f"(f), "r"(i))
#define UNPACKFI(f, i, v) asm("mov.b64 {%0, %1}, %2;" : "=f"(f), "=r"(i) : "l"(v))

// ---------------- scratch ----------------
__device__ float g_tau [2 * B_Q];
__device__ int   g_cnt [2 * B_Q];
__device__ u64   g_f   [(size_t)2 * B_Q * CAP];   // packed (float score, int idx)

// ---------------- helpers ----------------
template <int S>
__device__ __forceinline__ void sinsN(float (&rv)[S], int (&ri)[S], float s, int j) {
    float cv = s; int ci = j;
    #pragma unroll
    for (int k = 0; k < S; k++) {
        bool sm = cv < rv[k];
        float tv = rv[k]; int ti = ri[k];
        rv[k] = sm ? cv : rv[k];
        ri[k] = sm ? ci : ri[k];
        cv = sm ? tv : cv;
        ci = sm ? ti : ci;
    }
}

template <int S>
__device__ __forceinline__ void popN(float (&rv)[S], int (&ri)[S]) {
    #pragma unroll
    for (int k = 0; k < S - 1; k++) { rv[k] = rv[k + 1]; ri[k] = ri[k + 1]; }
    rv[S - 1] = FLT_BIG; ri[S - 1] = 0;
}

__device__ __forceinline__ void wmin(float& v, int& id, int& ln) {
    #pragma unroll
    for (int off = 16; off; off >>= 1) {
        float ov = __shfl_xor_sync(FULLMASK, v,  off);
        int  oid = __shfl_xor_sync(FULLMASK, id, off);
        int  oln = __shfl_xor_sync(FULLMASK, ln, off);
        if (ov < v) { v = ov; id = oid; ln = oln; }
    }
}

__device__ __forceinline__ void wminv(float& v) {
    #pragma unroll
    for (int off = 16; off; off >>= 1) {
        float ov = __shfl_xor_sync(FULLMASK, v, off);
        v = (ov < v) ? ov : v;
    }
}

__device__ __forceinline__ void load_q_neg2(const float* emb, int self, u64 (&an)[8]) {
    const float4* av = reinterpret_cast<const float4*>(emb) + (size_t)self * 4;
    float4 a0 = av[0], a1 = av[1], a2 = av[2], a3 = av[3];
    PACK2(an[0], -a0.x, -a0.y); PACK2(an[1], -a0.z, -a0.w);
    PACK2(an[2], -a1.x, -a1.y); PACK2(an[3], -a1.z, -a1.w);
    PACK2(an[4], -a2.x, -a2.y); PACK2(an[5], -a2.z, -a2.w);
    PACK2(an[6], -a3.x, -a3.y); PACK2(an[7], -a3.z, -a3.w);
}

// score = 0.5|e|^2 - a.e with acc pre-init (0.5n, 0); two accumulator chains
__device__ __forceinline__ float score8(const ulonglong2* __restrict__ e2, const u64 an[8], u64 acc0) {
    ulonglong2 u0 = e2[0], u1 = e2[1], u2 = e2[2], u3 = e2[3];
    u64 acc1 = 0ull;
    FMA2(acc0, u0.x, an[0], acc0); FMA2(acc1, u0.y, an[1], acc1);
    FMA2(acc0, u1.x, an[2], acc0); FMA2(acc1, u1.y, an[3], acc1);
    FMA2(acc0, u2.x, an[4], acc0); FMA2(acc1, u2.y, an[5], acc1);
    FMA2(acc0, u3.x, an[6], acc0); FMA2(acc1, u3.y, an[7], acc1);
    float l0, h0, l1, h1;
    UNPACK2(l0, h0, acc0);
    UNPACK2(l1, h1, acc1);
    return (l0 + h0) + (l1 + h1);
}

// ============ kernel A: per-(pass,query) tau — block per query, 4 warps split window ============
__global__ __launch_bounds__(128) void prep_kernel(
    const float* __restrict__ emb0, const float* __restrict__ emb1,
    const int* __restrict__ idx0, const int* __restrict__ idx1)
{
    __shared__ float sv[32];

    const int tid  = threadIdx.x;
    const int wid  = tid >> 5;
    const int lane = tid & 31;
    const int w    = blockIdx.x;            // [0,1024)
    const int pass = w >> 9;
    const int q    = w & (B_Q - 1);

    const float* emb  = pass ? emb1 : emb0;
    const int    self = (pass ? idx1 : idx0)[q];

    u64 an[8];
    load_q_neg2(emb, self, an);
    u64 halfp;
    PACK2(halfp, 0.5f, 0.5f);

    float rv[8]; int ri[8];
    #pragma unroll
    for (int k = 0; k < 8; k++) { rv[k] = FLT_BIG; ri[k] = 0; }

    const ulonglong2* emb2 = reinterpret_cast<const ulonglong2*>(emb);

    #pragma unroll 2
    for (int i = 0; i < 8; i++) {
        int j = wid * 256 + i * 32 + lane;
        const ulonglong2* p = emb2 + (size_t)j * 4;
        ulonglong2 u0 = p[0], u1 = p[1], u2 = p[2], u3 = p[3];
        u64 h0, h1, h2, h3, h4, h5, h6, h7;
        FMA2(h0, u0.x, halfp, an[0]); FMA2(h1, u0.y, halfp, an[1]);
        FMA2(h2, u1.x, halfp, an[2]); FMA2(h3, u1.y, halfp, an[3]);
        FMA2(h4, u2.x, halfp, an[4]); FMA2(h5, u2.y, halfp, an[5]);
        FMA2(h6, u3.x, halfp, an[6]); FMA2(h7, u3.y, halfp, an[7]);
        u64 acc0 = 0ull, acc1 = 0ull;
        FMA2(acc0, u0.x, h0, acc0); FMA2(acc1, u0.y, h1, acc1);
        FMA2(acc0, u1.x, h2, acc0); FMA2(acc1, u1.y, h3, acc1);
        FMA2(acc0, u2.x, h4, acc0); FMA2(acc1, u2.y, h5, acc1);
        FMA2(acc0, u3.x, h6, acc0); FMA2(acc1, u3.y, h7, acc1);
        float l0, hh0, l1, hh1;
        UNPACK2(l0, hh0, acc0);
        UNPACK2(l1, hh1, acc1);
        float s = (l0 + hh0) + (l1 + hh1);
        if (s < rv[7] && j != self) sinsN<8>(rv, ri, s, j);
    }

    #pragma unroll
    for (int r = 0; r < 8; r++) {
        float v = rv[0]; int id = ri[0]; int ln = lane;
        wmin(v, id, ln);
        if (lane == ln) popN<8>(rv, ri);
        if (lane == 0) sv[wid * 8 + r] = v;
    }
    __syncthreads();

    if (wid == 0) {
        float v = sv[lane];
        float tau = 0.f;
        #pragma unroll
        for (int r = 0; r < 8; r++) {
            float mv = v;
            wminv(mv);
            tau = mv;
            if (v == mv) v = FLT_BIG;
        }
        if (lane == 0) { g_tau[w] = tau; g_cnt[w] = 0; }
    }
}

// ============ kernel B: filter — branch-free survivor push, exact tile bounds ============
__global__ __launch_bounds__(QPB) void filter_kernel(
    const float* __restrict__ emb0, const float* __restrict__ emb1,
    const int* __restrict__ idx0, const int* __restrict__ idx1)
{
    __shared__ float4 smE[TILE * 4];        // 16KB
    __shared__ u64    smN[TILE];            // 2KB packed (0.5n, 0)
    __shared__ u64    sbuf[BUFD * QPB];     // 16KB, layout [slot][tid]

    const int chunk = blockIdx.x;
    const int qg    = blockIdx.y;
    const int pass  = blockIdx.z;
    const int tid   = threadIdx.x;

    const float* emb = pass ? emb1 : emb0;
    const float4* emb4 = reinterpret_cast<const float4*>(emb);

    const int q    = qg * QPB + tid;
    const int t2   = pass * B_Q + q;
    const int self = (pass ? idx1 : idx0)[q];
    const float tau = g_tau[t2];

    u64 an[8];
    load_q_neg2(emb, self, an);

    const int c0 = chunk * CHUNK;
    const int c1 = min(c0 + CHUNK, N_EMB);

    for (int base = c0; base < c1; base += TILE) {
        const int nvalid = c1 - base;
        const int ncp = (min(TILE, nvalid) + 3) & ~3;   // exact padded bound
        __syncthreads();
        for (int c = tid; c < ncp; c += QPB) {
            int gj = base + c;
            if (c < nvalid) {
                const float4* gE = emb4 + (size_t)gj * 4;
                float4 v0 = gE[0], v1 = gE[1], v2 = gE[2], v3 = gE[3];
                smE[4*c] = v0; smE[4*c+1] = v1; smE[4*c+2] = v2; smE[4*c+3] = v3;
                float s = v0.x*v0.x + v0.y*v0.y + v0.z*v0.z + v0.w*v0.w
                        + v1.x*v1.x + v1.y*v1.y + v1.z*v1.z + v1.w*v1.w
                        + v2.x*v2.x + v2.y*v2.y + v2.z*v2.z + v2.w*v2.w
                        + v3.x*v3.x + v3.y*v3.y + v3.z*v3.z + v3.w*v3.w;
                u64 pn; PACK2(pn, 0.5f * s, 0.f);
                smN[c] = pn;
            } else {
                float4 z = make_float4(0.f, 0.f, 0.f, 0.f);
                smE[4*c] = z; smE[4*c+1] = z; smE[4*c+2] = z; smE[4*c+3] = z;
                u64 pn; PACK2(pn, FLT_BIG, 0.f);
                smN[c] = pn;
            }
        }
        __syncthreads();

        const ulonglong2* smE2 = reinterpret_cast<const ulonglong2*>(smE);
        int cnt = 0;

        #pragma unroll 1
        for (int cc = 0; cc < ncp; cc += 4) {
            float s0 = score8(&smE2[4*cc],      an, smN[cc]);
            float s1 = score8(&smE2[4*cc + 4],  an, smN[cc + 1]);
            float s2 = score8(&smE2[4*cc + 8],  an, smN[cc + 2]);
            float s3 = score8(&smE2[4*cc + 12], an, smN[cc + 3]);

            u64 v;
            PACKFI(v, s0, base + cc);
            sbuf[min(cnt, BUFD - 1) * QPB + tid] = v;  cnt += (s0 <= tau);
            PACKFI(v, s1, base + cc + 1);
            sbuf[min(cnt, BUFD - 1) * QPB + tid] = v;  cnt += (s1 <= tau);
            PACKFI(v, s2, base + cc + 2);
            sbuf[min(cnt, BUFD - 1) * QPB + tid] = v;  cnt += (s2 <= tau);
            PACKFI(v, s3, base + cc + 3);
            sbuf[min(cnt, BUFD - 1) * QPB + tid] = v;  cnt += (s3 <= tau);
        }

        if (cnt > 0) {
            if (cnt > BUFD) cnt = BUFD;
            int slot = atomicAdd(&g_cnt[t2], cnt);
            for (int k = 0; k < cnt; k++) {
                int o = slot + k;
                if (o < CAP) g_f[(size_t)t2 * CAP + o] = sbuf[k * QPB + tid];
            }
        }
    }
}

// ============ kernel C: exact top-20 of survivors + features + fused MLP ============
__global__ __launch_bounds__(128) void select_kernel(
    const float* __restrict__ emb0, const float* __restrict__ emb1,
    const float* __restrict__ rctx0, const float* __restrict__ rctx1,
    const int* __restrict__ idx0, const int* __restrict__ idx1,
    const float* __restrict__ mean_in, const float* __restrict__ std_in,
    const float* __restrict__ W1, const float* __restrict__ b1,
    const float* __restrict__ Wm, const float* __restrict__ bm,
    const float* __restrict__ Ws, const float* __restrict__ bs,
    float* __restrict__ out)
{
    __shared__ float sfe[2][8];

    const int wid  = threadIdx.x >> 5;
    const int lane = threadIdx.x & 31;
    const int ql   = wid >> 1;
    const int pass = wid & 1;
    const int q    = blockIdx.x * 2 + ql;
    const int t2   = pass * B_Q + q;

    const float* rctx = pass ? rctx1 : rctx0;
    const float* emb  = pass ? emb1 : emb0;
    const int    self = (pass ? idx1 : idx0)[q];

    float na;
    {
        const float4* av = reinterpret_cast<const float4*>(emb) + (size_t)self * 4;
        float4 a0 = av[0], a1 = av[1], a2 = av[2], a3 = av[3];
        na = a0.x*a0.x + a0.y*a0.y + a0.z*a0.z + a0.w*a0.w
           + a1.x*a1.x + a1.y*a1.y + a1.z*a1.z + a1.w*a1.w
           + a2.x*a2.x + a2.y*a2.y + a2.z*a2.z + a2.w*a2.w
           + a3.x*a3.x + a3.y*a3.y + a3.z*a3.z + a3.w*a3.w;
    }

    int cnt = g_cnt[t2];
    if (cnt > CAP) cnt = CAP;

    float rv[10]; int ri[10];
    #pragma unroll
    for (int k = 0; k < 10; k++) { rv[k] = FLT_BIG; ri[k] = 0; }
    const u64* GF = g_f + (size_t)t2 * CAP;
    for (int i = lane; i < cnt; i += 32) {
        u64 v = GF[i];
        float s; int j;
        UNPACKFI(s, j, v);
        if (s < rv[9] && j != self) sinsN<10>(rv, ri, s, j);
    }

    float ms = 0.f; int mj = 0;
    #pragma unroll
    for (int r = 0; r < K_NN; r++) {
        float v = rv[0]; int id = ri[0]; int ln = lane;
        wmin(v, id, ln);
        if (lane == ln) popN<10>(rv, ri);
        if (lane == r) { ms = v; mj = id; }
    }

    const bool act = lane < K_NN;
    float w = 0.f, y = 0.f;
    if (act) {
        float d2 = fmaxf(fmaf(2.f, ms, na), 0.f);
        w = expf(-(sqrtf(d2) + 0.001f));
        y = rctx[(size_t)q * N_EMB + mj];
    }
    float f1 = w, f2n = w * y, ysum = y;
    #pragma unroll
    for (int off = 16; off; off >>= 1) {
        f1   += __shfl_xor_sync(FULLMASK, f1,   off);
        f2n  += __shfl_xor_sync(FULLMASK, f2n,  off);
        ysum += __shfl_xor_sync(FULLMASK, ysum, off);
    }
    float mean = ysum * (1.0f / K_NN);
    float d = act ? (y - mean) : 0.f;
    float var = d * d;
    #pragma unroll
    for (int off = 16; off; off >>= 1) var += __shfl_xor_sync(FULLMASK, var, off);
    float f3 = sqrtf(var * (1.0f / (K_NN - 1)));

    if (lane == 0) {
        sfe[ql][pass]     = f1;
        sfe[ql][2 + pass] = f2n / f1;
        sfe[ql][4 + pass] = f3;
        if (pass == 0) {
            sfe[ql][6] = mean_in[q];
            sfe[ql][7] = std_in[q];
        }
    }
    __syncthreads();

    if (wid < 2) {
        const int mq = blockIdx.x * 2 + wid;
        float f[8];
        #pragma unroll
        for (int i = 0; i < 8; i++) f[i] = sfe[wid][i];

        float m = 0.f, sd = 0.f;
        #pragma unroll
        for (int half = 0; half < 2; half++) {
            int j = lane + half * 32;
            float acc = b1[j];
            #pragma unroll
            for (int i = 0; i < 8; i++) acc = fmaf(f[i], W1[i * 64 + j], acc);
            float h = fmaxf(acc, 0.f);
            m  = fmaf(h, Wm[j], m);
            sd = fmaf(h, Ws[j], sd);
        }
        #pragma unroll
        for (int off = 16; off; off >>= 1) {
            m  += __shfl_xor_sync(FULLMASK, m,  off);
            sd += __shfl_xor_sync(FULLMASK, sd, off);
        }
        if (lane == 0) {
            out[mq]       = m  + bm[0];
            out[B_Q + mq] = sd + bs[0];
        }
    }
}

// ---------------- launcher ----------------
extern "C" void kernel_launch(void* const* d_in, const int* in_sizes, int n_in,
                              void* d_out, int out_size)
{
    const float* emb0    = (const float*)d_in[0];
    const float* emb1    = (const float*)d_in[1];
    const float* rctx0   = (const float*)d_in[2];
    const float* rctx1   = (const float*)d_in[3];
    const int*   idx0    = (const int*)d_in[4];
    const int*   idx1    = (const int*)d_in[5];
    const float* mean_in = (const float*)d_in[6];
    const float* std_in  = (const float*)d_in[7];
    const float* W1      = (const float*)d_in[8];
    const float* b1      = (const float*)d_in[9];
    const float* Wm      = (const float*)d_in[10];
    const float* bm      = (const float*)d_in[11];
    const float* Ws      = (const float*)d_in[12];
    const float* bs      = (const float*)d_in[13];
    float* out = (float*)d_out;

    prep_kernel<<<2 * B_Q, 128>>>(emb0, emb1, idx0, idx1);

    dim3 g1(NCHUNK, B_Q / QPB, 2);
    filter_kernel<<<g1, QPB>>>(emb0, emb1, idx0, idx1);

    select_kernel<<<B_Q / 2, 128>>>(emb0, emb1, rctx0, rctx1, idx0, idx1,
                                    mean_in, std_in,
                                    W1, b1, Wm, bm, Ws, bs, out);
}

// round 15
// speedup vs baseline: 1.7599x; 1.1100x over previous
#include <cuda_runtime.h>

// ---------------- problem constants ----------------
#define N_EMB   50000
#define B_Q     512
#define E_DIM   16
#define K_NN    20
#define NCHUNK  128
#define CHUNK   391           // 128*391 = 50048 >= 50000; tiles 256 + 135(pad->136)
#define TILE    256
#define QPB     128           // threads per filter block; each thread serves 2 queries
#define CAP     2048
#define BUFD    14            // per-thread per-query smem survivor slots per tile (Poisson(2) tail safe)
#define WIN     1024          // prep sample window
#define FLT_BIG 3.402823466e+38f
#define FULLMASK 0xffffffffu

typedef unsigned long long u64;

// packed f32x2 helpers
#define FMA2(d, a, b, c) asm("fma.rn.f32x2 %0, %1, %2, %3;" : "=l"(d) : "l"(a), "l"(b), "l"(c))
#define ADD2(d, a, b)    asm("add.rn.f32x2 %0, %1, %2;" : "=l"(d) : "l"(a), "l"(b))
#define PACK2(d, lo, hi) asm("mov.b64 %0, {%1, %2};" : "=l"(d) : "f"(lo), "f"(hi))
#define UNPACK2(lo, hi, v) asm("mov.b64 {%0, %1}, %2;" : "=f"(lo), "=f"(hi) : "l"(v))
#define PACKFI(d, f, i) asm("mov.b64 %0, {%1, %2};" : "=l"(d) : "f"(f), "r"(i))
#define UNPACKFI(f, i, v) asm("mov.b64 {%0, %1}, %2;" : "=f"(f), "=r"(i) : "l"(v))

// ---------------- scratch ----------------
__device__ float g_tau [2 * B_Q];
__device__ int   g_cnt [2 * B_Q];
__device__ u64   g_f   [(size_t)2 * B_Q * CAP];   // packed (float score, int idx)

// ---------------- helpers ----------------
template <int S>
__device__ __forceinline__ void sinsN(float (&rv)[S], int (&ri)[S], float s, int j) {
    float cv = s; int ci = j;
    #pragma unroll
    for (int k = 0; k < S; k++) {
        bool sm = cv < rv[k];
        float tv = rv[k]; int ti = ri[k];
        rv[k] = sm ? cv : rv[k];
        ri[k] = sm ? ci : ri[k];
        cv = sm ? tv : cv;
        ci = sm ? ti : ci;
    }
}

template <int S>
__device__ __forceinline__ void popN(float (&rv)[S], int (&ri)[S]) {
    #pragma unroll
    for (int k = 0; k < S - 1; k++) { rv[k] = rv[k + 1]; ri[k] = ri[k + 1]; }
    rv[S - 1] = FLT_BIG; ri[S - 1] = 0;
}

__device__ __forceinline__ void wmin(float& v, int& id, int& ln) {
    #pragma unroll
    for (int off = 16; off; off >>= 1) {
        float ov = __shfl_xor_sync(FULLMASK, v,  off);
        int  oid = __shfl_xor_sync(FULLMASK, id, off);
        int  oln = __shfl_xor_sync(FULLMASK, ln, off);
        if (ov < v) { v = ov; id = oid; ln = oln; }
    }
}

__device__ __forceinline__ void wminv(float& v) {
    #pragma unroll
    for (int off = 16; off; off >>= 1) {
        float ov = __shfl_xor_sync(FULLMASK, v, off);
        v = (ov < v) ? ov : v;
    }
}

__device__ __forceinline__ void load_q_neg2(const float* emb, int self, u64 (&an)[8]) {
    const float4* av = reinterpret_cast<const float4*>(emb) + (size_t)self * 4;
    float4 a0 = av[0], a1 = av[1], a2 = av[2], a3 = av[3];
    PACK2(an[0], -a0.x, -a0.y); PACK2(an[1], -a0.z, -a0.w);
    PACK2(an[2], -a1.x, -a1.y); PACK2(an[3], -a1.z, -a1.w);
    PACK2(an[4], -a2.x, -a2.y); PACK2(an[5], -a2.z, -a2.w);
    PACK2(an[6], -a3.x, -a3.y); PACK2(an[7], -a3.z, -a3.w);
}

// two query scores sharing one candidate's loads; acc pre-init (0.5n, 0)
__device__ __forceinline__ void score8x2(
    const ulonglong2* __restrict__ e2,
    const u64 an0[8], const u64 an1[8], u64 pn,
    float& s0, float& s1)
{
    ulonglong2 u0 = e2[0], u1 = e2[1], u2 = e2[2], u3 = e2[3];
    u64 p0 = pn, p1 = 0ull, q0 = pn, q1 = 0ull;
    FMA2(p0, u0.x, an0[0], p0); FMA2(p1, u0.y, an0[1], p1);
    FMA2(q0, u0.x, an1[0], q0); FMA2(q1, u0.y, an1[1], q1);
    FMA2(p0, u1.x, an0[2], p0); FMA2(p1, u1.y, an0[3], p1);
    FMA2(q0, u1.x, an1[2], q0); FMA2(q1, u1.y, an1[3], q1);
    FMA2(p0, u2.x, an0[4], p0); FMA2(p1, u2.y, an0[5], p1);
    FMA2(q0, u2.x, an1[4], q0); FMA2(q1, u2.y, an1[5], q1);
    FMA2(p0, u3.x, an0[6], p0); FMA2(p1, u3.y, an0[7], p1);
    FMA2(q0, u3.x, an1[6], q0); FMA2(q1, u3.y, an1[7], q1);
    u64 ps, qs;
    ADD2(ps, p0, p1);
    ADD2(qs, q0, q1);
    float l, h;
    UNPACK2(l, h, ps); s0 = l + h;
    UNPACK2(l, h, qs); s1 = l + h;
}

// ============ kernel A: per-(pass,query) tau — block per query, 4 warps split window ============
__global__ __launch_bounds__(128) void prep_kernel(
    const float* __restrict__ emb0, const float* __restrict__ emb1,
    const int* __restrict__ idx0, const int* __restrict__ idx1)
{
    __shared__ float sv[32];

    const int tid  = threadIdx.x;
    const int wid  = tid >> 5;
    const int lane = tid & 31;
    const int w    = blockIdx.x;            // [0,1024)
    const int pass = w >> 9;
    const int q    = w & (B_Q - 1);

    const float* emb  = pass ? emb1 : emb0;
    const int    self = (pass ? idx1 : idx0)[q];

    u64 an[8];
    load_q_neg2(emb, self, an);
    u64 halfp;
    PACK2(halfp, 0.5f, 0.5f);

    float rv[8]; int ri[8];
    #pragma unroll
    for (int k = 0; k < 8; k++) { rv[k] = FLT_BIG; ri[k] = 0; }

    const ulonglong2* emb2 = reinterpret_cast<const ulonglong2*>(emb);

    #pragma unroll 2
    for (int i = 0; i < 8; i++) {
        int j = wid * 256 + i * 32 + lane;
        const ulonglong2* p = emb2 + (size_t)j * 4;
        ulonglong2 u0 = p[0], u1 = p[1], u2 = p[2], u3 = p[3];
        u64 h0, h1, h2, h3, h4, h5, h6, h7;
        FMA2(h0, u0.x, halfp, an[0]); FMA2(h1, u0.y, halfp, an[1]);
        FMA2(h2, u1.x, halfp, an[2]); FMA2(h3, u1.y, halfp, an[3]);
        FMA2(h4, u2.x, halfp, an[4]); FMA2(h5, u2.y, halfp, an[5]);
        FMA2(h6, u3.x, halfp, an[6]); FMA2(h7, u3.y, halfp, an[7]);
        u64 acc0 = 0ull, acc1 = 0ull;
        FMA2(acc0, u0.x, h0, acc0); FMA2(acc1, u0.y, h1, acc1);
        FMA2(acc0, u1.x, h2, acc0); FMA2(acc1, u1.y, h3, acc1);
        FMA2(acc0, u2.x, h4, acc0); FMA2(acc1, u2.y, h5, acc1);
        FMA2(acc0, u3.x, h6, acc0); FMA2(acc1, u3.y, h7, acc1);
        u64 accs;
        ADD2(accs, acc0, acc1);
        float l0, hh0;
        UNPACK2(l0, hh0, accs);
        float s = l0 + hh0;
        if (s < rv[7] && j != self) sinsN<8>(rv, ri, s, j);
    }

    #pragma unroll
    for (int r = 0; r < 8; r++) {
        float v = rv[0]; int id = ri[0]; int ln = lane;
        wmin(v, id, ln);
        if (lane == ln) popN<8>(rv, ri);
        if (lane == 0) sv[wid * 8 + r] = v;
    }
    __syncthreads();

    if (wid == 0) {
        float v = sv[lane];
        float tau = 0.f;
        #pragma unroll
        for (int r = 0; r < 8; r++) {
            float mv = v;
            wminv(mv);
            tau = mv;
            if (v == mv) v = FLT_BIG;
        }
        if (lane == 0) { g_tau[w] = tau; g_cnt[w] = 0; }
    }
}

// ============ kernel B: filter — 2 queries per thread, branch-free survivor push ============
__global__ __launch_bounds__(QPB) void filter_kernel(
    const float* __restrict__ emb0, const float* __restrict__ emb1,
    const int* __restrict__ idx0, const int* __restrict__ idx1)
{
    __shared__ float4 smE[TILE * 4];            // 16KB
    __shared__ u64    smN[TILE];                // 2KB packed (0.5n, 0)
    __shared__ u64    sbuf[BUFD * 2 * QPB];     // 28KB, layout [slot][query][tid]

    const int chunk = blockIdx.x;
    const int qg    = blockIdx.y;               // 0/1 -> queries [qg*256, qg*256+256)
    const int pass  = blockIdx.z;
    const int tid   = threadIdx.x;

    const float* emb = pass ? emb1 : emb0;
    const float4* emb4 = reinterpret_cast<const float4*>(emb);
    const int* idxA = pass ? idx1 : idx0;

    const int q0  = qg * 256 + tid;
    const int q1  = q0 + 128;
    const int t20 = pass * B_Q + q0;
    const int t21 = pass * B_Q + q1;
    const float tau0 = g_tau[t20];
    const float tau1 = g_tau[t21];

    u64 an0[8], an1[8];
    load_q_neg2(emb, idxA[q0], an0);
    load_q_neg2(emb, idxA[q1], an1);

    const int c0 = chunk * CHUNK;
    const int c1 = min(c0 + CHUNK, N_EMB);

    for (int base = c0; base < c1; base += TILE) {
        const int nvalid = c1 - base;
        const int ncp = (min(TILE, nvalid) + 3) & ~3;   // exact padded bound
        __syncthreads();
        for (int c = tid; c < ncp; c += QPB) {
            int gj = base + c;
            if (c < nvalid) {
                const float4* gE = emb4 + (size_t)gj * 4;
                float4 v0 = gE[0], v1 = gE[1], v2 = gE[2], v3 = gE[3];
                smE[4*c] = v0; smE[4*c+1] = v1; smE[4*c+2] = v2; smE[4*c+3] = v3;
                float s = v0.x*v0.x + v0.y*v0.y + v0.z*v0.z + v0.w*v0.w
                        + v1.x*v1.x + v1.y*v1.y + v1.z*v1.z + v1.w*v1.w
                        + v2.x*v2.x + v2.y*v2.y + v2.z*v2.z + v2.w*v2.w
                        + v3.x*v3.x + v3.y*v3.y + v3.z*v3.z + v3.w*v3.w;
                u64 pn; PACK2(pn, 0.5f * s, 0.f);
                smN[c] = pn;
            } else {
                float4 z = make_float4(0.f, 0.f, 0.f, 0.f);
                smE[4*c] = z; smE[4*c+1] = z; smE[4*c+2] = z; smE[4*c+3] = z;
                u64 pn; PACK2(pn, FLT_BIG, 0.f);
                smN[c] = pn;
            }
        }
        __syncthreads();

        const ulonglong2* smE2 = reinterpret_cast<const ulonglong2*>(smE);
        int cnt0 = 0, cnt1 = 0;

        #pragma unroll 1
        for (int cc = 0; cc < ncp; cc += 2) {
            float s00, s01, s10, s11;
            score8x2(&smE2[4*cc],     an0, an1, smN[cc],     s00, s01);
            score8x2(&smE2[4*cc + 4], an0, an1, smN[cc + 1], s10, s11);

            u64 v;
            PACKFI(v, s00, base + cc);
            sbuf[(min(cnt0, BUFD - 1) * 2 + 0) * QPB + tid] = v;  cnt0 += (s00 <= tau0);
            PACKFI(v, s01, base + cc);
            sbuf[(min(cnt1, BUFD - 1) * 2 + 1) * QPB + tid] = v;  cnt1 += (s01 <= tau1);
            PACKFI(v, s10, base + cc + 1);
            sbuf[(min(cnt0, BUFD - 1) * 2 + 0) * QPB + tid] = v;  cnt0 += (s10 <= tau0);
            PACKFI(v, s11, base + cc + 1);
            sbuf[(min(cnt1, BUFD - 1) * 2 + 1) * QPB + tid] = v;  cnt1 += (s11 <= tau1);
        }

        if (cnt0 > 0) {
            if (cnt0 > BUFD) cnt0 = BUFD;
            int slot = atomicAdd(&g_cnt[t20], cnt0);
            for (int k = 0; k < cnt0; k++) {
                int o = slot + k;
                if (o < CAP) g_f[(size_t)t20 * CAP + o] = sbuf[(k * 2 + 0) * QPB + tid];
            }
        }
        if (cnt1 > 0) {
            if (cnt1 > BUFD) cnt1 = BUFD;
            int slot = atomicAdd(&g_cnt[t21], cnt1);
            for (int k = 0; k < cnt1; k++) {
                int o = slot + k;
                if (o < CAP) g_f[(size_t)t21 * CAP + o] = sbuf[(k * 2 + 1) * QPB + tid];
            }
        }
    }
}

// ============ kernel C: exact top-20 of survivors + features + fused MLP ============
__global__ __launch_bounds__(128) void select_kernel(
    const float* __restrict__ emb0, const float* __restrict__ emb1,
    const float* __restrict__ rctx0, const float* __restrict__ rctx1,
    const int* __restrict__ idx0, const int* __restrict__ idx1,
    const float* __restrict__ mean_in, const float* __restrict__ std_in,
    const float* __restrict__ W1, const float* __restrict__ b1,
    const float* __restrict__ Wm, const float* __restrict__ bm,
    const float* __restrict__ Ws, const float* __restrict__ bs,
    float* __restrict__ out)
{
    __shared__ float sfe[2][8];

    const int wid  = threadIdx.x >> 5;
    const int lane = threadIdx.x & 31;
    const int ql   = wid >> 1;
    const int pass = wid & 1;
    const int q    = blockIdx.x * 2 + ql;
    const int t2   = pass * B_Q + q;

    const float* rctx = pass ? rctx1 : rctx0;
    const float* emb  = pass ? emb1 : emb0;
    const int    self = (pass ? idx1 : idx0)[q];

    float na;
    {
        const float4* av = reinterpret_cast<const float4*>(emb) + (size_t)self * 4;
        float4 a0 = av[0], a1 = av[1], a2 = av[2], a3 = av[3];
        na = a0.x*a0.x + a0.y*a0.y + a0.z*a0.z + a0.w*a0.w
           + a1.x*a1.x + a1.y*a1.y + a1.z*a1.z + a1.w*a1.w
           + a2.x*a2.x + a2.y*a2.y + a2.z*a2.z + a2.w*a2.w
           + a3.x*a3.x + a3.y*a3.y + a3.z*a3.z + a3.w*a3.w;
    }

    int cnt = g_cnt[t2];
    if (cnt > CAP) cnt = CAP;

    float rv[10]; int ri[10];
    #pragma unroll
    for (int k = 0; k < 10; k++) { rv[k] = FLT_BIG; ri[k] = 0; }
    const u64* GF = g_f + (size_t)t2 * CAP;
    for (int i = lane; i < cnt; i += 32) {
        u64 v = GF[i];
        float s; int j;
        UNPACKFI(s, j, v);
        if (s < rv[9] && j != self) sinsN<10>(rv, ri, s, j);
    }

    float ms = 0.f; int mj = 0;
    #pragma unroll
    for (int r = 0; r < K_NN; r++) {
        float v = rv[0]; int id = ri[0]; int ln = lane;
        wmin(v, id, ln);
        if (lane == ln) popN<10>(rv, ri);
        if (lane == r) { ms = v; mj = id; }
    }

    const bool act = lane < K_NN;
    float w = 0.f, y = 0.f;
    if (act) {
        float d2 = fmaxf(fmaf(2.f, ms, na), 0.f);
        w = expf(-(sqrtf(d2) + 0.001f));
        y = rctx[(size_t)q * N_EMB + mj];
    }
    float f1 = w, f2n = w * y, ysum = y;
    #pragma unroll
    for (int off = 16; off; off >>= 1) {
        f1   += __shfl_xor_sync(FULLMASK, f1,   off);
        f2n  += __shfl_xor_sync(FULLMASK, f2n,  off);
        ysum += __shfl_xor_sync(FULLMASK, ysum, off);
    }
    float mean = ysum * (1.0f / K_NN);
    float d = act ? (y - mean) : 0.f;
    float var = d * d;
    #pragma unroll
    for (int off = 16; off; off >>= 1) var += __shfl_xor_sync(FULLMASK, var, off);
    float f3 = sqrtf(var * (1.0f / (K_NN - 1)));

    if (lane == 0) {
        sfe[ql][pass]     = f1;
        sfe[ql][2 + pass] = f2n / f1;
        sfe[ql][4 + pass] = f3;
        if (pass == 0) {
            sfe[ql][6] = mean_in[q];
            sfe[ql][7] = std_in[q];
        }
    }
    __syncthreads();

    if (wid < 2) {
        const int mq = blockIdx.x * 2 + wid;
        float f[8];
        #pragma unroll
        for (int i = 0; i < 8; i++) f[i] = sfe[wid][i];

        float m = 0.f, sd = 0.f;
        #pragma unroll
        for (int half = 0; half < 2; half++) {
            int j = lane + half * 32;
            float acc = b1[j];
            #pragma unroll
            for (int i = 0; i < 8; i++) acc = fmaf(f[i], W1[i * 64 + j], acc);
            float h = fmaxf(acc, 0.f);
            m  = fmaf(h, Wm[j], m);
            sd = fmaf(h, Ws[j], sd);
        }
        #pragma unroll
        for (int off = 16; off; off >>= 1) {
            m  += __shfl_xor_sync(FULLMASK, m,  off);
            sd += __shfl_xor_sync(FULLMASK, sd, off);
        }
        if (lane == 0) {
            out[mq]       = m  + bm[0];
            out[B_Q + mq] = sd + bs[0];
        }
    }
}

// ---------------- launcher ----------------
extern "C" void kernel_launch(void* const* d_in, const int* in_sizes, int n_in,
                              void* d_out, int out_size)
{
    const float* emb0    = (const float*)d_in[0];
    const float* emb1    = (const float*)d_in[1];
    const float* rctx0   = (const float*)d_in[2];
    const float* rctx1   = (const float*)d_in[3];
    const int*   idx0    = (const int*)d_in[4];
    const int*   idx1    = (const int*)d_in[5];
    const float* mean_in = (const float*)d_in[6];
    const float* std_in  = (const float*)d_in[7];
    const float* W1      = (const float*)d_in[8];
    const float* b1      = (const float*)d_in[9];
    const float* Wm      = (const float*)d_in[10];
    const float* bm      = (const float*)d_in[11];
    const float* Ws      = (const float*)d_in[12];
    const float* bs      = (const float*)d_in[13];
    float* out = (float*)d_out;

    prep_kernel<<<2 * B_Q, 128>>>(emb0, emb1, idx0, idx1);

    dim3 g1(NCHUNK, 2, 2);
    filter_kernel<<<g1, QPB>>>(emb0, emb1, idx0, idx1);

    select_kernel<<<B_Q / 2, 128>>>(emb0, emb1, rctx0, rctx1, idx0, idx1,
                                    mean_in, std_in,
                                    W1, b1, Wm, bm, Ws, bs, out);
}